// round 12
// baseline (speedup 1.0000x reference)
#include <cuda_runtime.h>
#include <cstdint>

#define DIMC   256
#define INNER  512
#define HH     56
#define HW     3136        // 56*56
#define BATCH  16

// GEMM tiles
#define BM 128
#define BN 112
#define BK 32
#define AST 36     // As row stride (floats): frag banks = (4g+tig)%32 all-distinct
#define BST 120    // Bs row stride (floats): frag banks = (24tig+g)%32 all-distinct
#define BUF_FLOATS (BM * AST + BK * BST)   // 4608 + 3840 = 8448

// ---------------- scratch (static device globals; no allocation) ----------------
__device__ float g_yq[(size_t)BATCH * DIMC  * HW];
__device__ float g_yk[(size_t)BATCH * DIMC  * HW];
__device__ float g_yv[(size_t)BATCH * DIMC  * HW];
__device__ float g_q[(size_t)BATCH * INNER * HW];
__device__ float g_k[(size_t)BATCH * INNER * HW];
__device__ float g_v[(size_t)BATCH * INNER * HW];
__device__ float g_o[(size_t)BATCH * INNER * HW];

// ---------------- fused 3x depthwise 3x3 conv + BN (eval) ----------------
__global__ void dw_bn3_kernel(const float* __restrict__ x,
                              const float* __restrict__ qw, const float* __restrict__ qg,
                              const float* __restrict__ qb, const float* __restrict__ qm,
                              const float* __restrict__ qv,
                              const float* __restrict__ kw, const float* __restrict__ kg,
                              const float* __restrict__ kb, const float* __restrict__ km,
                              const float* __restrict__ kv,
                              const float* __restrict__ vw, const float* __restrict__ vg,
                              const float* __restrict__ vb, const float* __restrict__ vm,
                              const float* __restrict__ vv)
{
    int idx = blockIdx.x * blockDim.x + threadIdx.x;
    int hw  = idx % HW;
    int bc  = idx / HW;
    int c   = bc % DIMC;
    int h   = hw / HH;
    int wq  = hw - h * HH;

    float qs = qg[c] * rsqrtf(qv[c] + 1e-5f);
    float qbe = qb[c] - qm[c] * qs;
    float ks = kg[c] * rsqrtf(kv[c] + 1e-5f);
    float kbe = kb[c] - km[c] * ks;
    float vs = vg[c] * rsqrtf(vv[c] + 1e-5f);
    float vbe = vb[c] - vm[c] * vs;

    const float* xp = x + (size_t)bc * HW;
    const float* qwp = qw + c * 9;
    const float* kwp = kw + c * 9;
    const float* vwp = vw + c * 9;

    float qa = 0.f, ka = 0.f, va = 0.f;
#pragma unroll
    for (int kh = 0; kh < 3; kh++) {
        int ih = h + kh - 1;
        if (ih < 0 || ih >= HH) continue;
#pragma unroll
        for (int kw2 = 0; kw2 < 3; kw2++) {
            int iw = wq + kw2 - 1;
            if (iw < 0 || iw >= HH) continue;
            float xv = xp[ih * HH + iw];
            int wi = kh * 3 + kw2;
            qa = fmaf(xv, qwp[wi], qa);
            ka = fmaf(xv, kwp[wi], ka);
            va = fmaf(xv, vwp[wi], va);
        }
    }
    g_yq[idx] = qa * qs + qbe;
    g_yk[idx] = ka * ks + kbe;
    g_yv[idx] = va * vs + vbe;
}

// ---------------- TF32 tensor-core GEMM, cp.async double-buffered, BK=32 ----------------
// C[b][m][p] = sum_k W[m][k] * SRC[b][k][p] (+bias)
// Block 128x112, 128 threads (2x2 warps), warp tile 64x56 = 4x7 m16n8k8.
// Dynamic smem: 2 buffers x 33.8KB. One __syncthreads per 32-deep K stage.

__device__ __forceinline__ uint32_t to_tf32(float x) {
    uint32_t u;
    asm("cvt.rna.tf32.f32 %0, %1;" : "=r"(u) : "f"(x));
    return u;
}

__device__ __forceinline__ void mma_tf32(float* d, const uint32_t* a, const uint32_t* b) {
    asm volatile(
        "mma.sync.aligned.m16n8k8.row.col.f32.tf32.tf32.f32 "
        "{%0,%1,%2,%3}, {%4,%5,%6,%7}, {%8,%9}, {%0,%1,%2,%3};\n"
        : "+f"(d[0]), "+f"(d[1]), "+f"(d[2]), "+f"(d[3])
        : "r"(a[0]), "r"(a[1]), "r"(a[2]), "r"(a[3]), "r"(b[0]), "r"(b[1]));
}

__device__ __forceinline__ void cp16(uint32_t dst, const void* src) {
    asm volatile("cp.async.cg.shared.global [%0], [%1], 16;\n" :: "r"(dst), "l"(src));
}
__device__ __forceinline__ void cpCommit() {
    asm volatile("cp.async.commit_group;\n" ::);
}
template<int N> __device__ __forceinline__ void cpWait() {
    asm volatile("cp.async.wait_group %0;\n" :: "n"(N));
}

extern __shared__ float smem_dyn[];

__global__ void __launch_bounds__(128, 3)
gemm_tf32_kernel(const float* __restrict__ W,
                 const float* __restrict__ bias,
                 const float* __restrict__ src,
                 float* __restrict__ dst,
                 int Kdim)
{
    float* As[2];   // [m][k] raw f32, stride AST
    float* Bs[2];   // [k][n] raw f32, stride BST
    As[0] = smem_dyn;
    Bs[0] = smem_dyn + BM * AST;
    As[1] = smem_dyn + BUF_FLOATS;
    Bs[1] = smem_dyn + BUF_FLOATS + BM * AST;

    int b     = blockIdx.z;
    int nBase = blockIdx.x * BN;
    int mBase = blockIdx.y * BM;

    const float* Bb = src + (size_t)b * Kdim * HW;

    int t    = threadIdx.x;
    int wid  = t >> 5;
    int lane = t & 31;
    int g    = lane >> 2;
    int tig  = lane & 3;
    int m0   = (wid >> 1) * 64;
    int n0   = (wid & 1) * 56;

    const float* aPtr = W + (size_t)(mBase + t) * Kdim;   // thread owns A row m=t (32 k's)

    uint32_t sAb[2], sBb[2];
    sAb[0] = (uint32_t)__cvta_generic_to_shared(As[0]);
    sAb[1] = (uint32_t)__cvta_generic_to_shared(As[1]);
    sBb[0] = (uint32_t)__cvta_generic_to_shared(Bs[0]);
    sBb[1] = (uint32_t)__cvta_generic_to_shared(Bs[1]);

    // B load mapping: 896 float4 chunks per stage (32 rows x 28 chunks), 128 threads -> 7 each
    int bRow[7], bC[7];
#pragma unroll
    for (int i = 0; i < 7; i++) {
        int ci = t + 128 * i;
        bRow[i] = ci / 28;
        bC[i]   = ci - bRow[i] * 28;
    }

    float acc[4][7][4];
#pragma unroll
    for (int i = 0; i < 4; i++)
#pragma unroll
        for (int j = 0; j < 7; j++)
#pragma unroll
            for (int r = 0; r < 4; r++) acc[i][j][r] = 0.f;

    int nStages = Kdim >> 5;

#define LOAD_STAGE(K0, BUF)                                                         \
    {                                                                               \
        uint32_t ad = sAb[BUF] + t * (AST * 4);                                     \
        _Pragma("unroll")                                                           \
        for (int q = 0; q < 8; q++)                                                 \
            cp16(ad + q * 16, aPtr + (K0) + 4 * q);                                 \
        _Pragma("unroll")                                                           \
        for (int i = 0; i < 7; i++)                                                 \
            cp16(sBb[BUF] + bRow[i] * (BST * 4) + bC[i] * 16,                       \
                 Bb + (size_t)((K0) + bRow[i]) * HW + nBase + bC[i] * 4);           \
    }

#define COMPUTE_STAGE(BUF)                                                          \
    {                                                                               \
        _Pragma("unroll")                                                           \
        for (int kk = 0; kk < 4; kk++) {                                            \
            int kb = kk * 8;                                                        \
            uint32_t af[4][4];                                                      \
            uint32_t bf[7][2];                                                      \
            _Pragma("unroll")                                                       \
            for (int im = 0; im < 4; im++) {                                        \
                const float* ap = &As[BUF][(m0 + 16 * im + g) * AST + kb + tig];    \
                af[im][0] = to_tf32(ap[0]);                                         \
                af[im][1] = to_tf32(ap[8 * AST]);                                   \
                af[im][2] = to_tf32(ap[4]);                                         \
                af[im][3] = to_tf32(ap[8 * AST + 4]);                               \
            }                                                                       \
            _Pragma("unroll")                                                       \
            for (int jn = 0; jn < 7; jn++) {                                        \
                const float* bp = &Bs[BUF][(kb + tig) * BST + n0 + 8 * jn + g];     \
                bf[jn][0] = to_tf32(bp[0]);                                         \
                bf[jn][1] = to_tf32(bp[4 * BST]);                                   \
            }                                                                       \
            _Pragma("unroll")                                                       \
            for (int im = 0; im < 4; im++)                                          \
                _Pragma("unroll")                                                   \
                for (int jn = 0; jn < 7; jn++)                                      \
                    mma_tf32(acc[im][jn], af[im], bf[jn]);                          \
        }                                                                           \
    }

    LOAD_STAGE(0, 0);
    cpCommit();

    // wait(s) -> sync -> issue loads for s+1 into drained slot -> compute s
    int buf = 0;
    for (int s = 0; s < nStages; s++) {
        cpWait<0>();
        __syncthreads();
        if (s + 1 < nStages) {
            LOAD_STAGE((s + 1) << 5, buf ^ 1);
            cpCommit();
        }
        COMPUTE_STAGE(buf);
        buf ^= 1;
    }

    // ---- epilogue ----
    float* Cb = dst + (size_t)b * (gridDim.y * BM) * HW;
#pragma unroll
    for (int im = 0; im < 4; im++) {
#pragma unroll
        for (int r2 = 0; r2 < 2; r2++) {
            int m = mBase + m0 + 16 * im + g + 8 * r2;
            float bi = bias ? bias[m] : 0.f;
#pragma unroll
            for (int jn = 0; jn < 7; jn++) {
                int n = nBase + n0 + 8 * jn + 2 * tig;
                float2 val = make_float2(acc[im][jn][2 * r2] + bi,
                                         acc[im][jn][2 * r2 + 1] + bi);
                *(float2*)(Cb + (size_t)m * HW + n) = val;
            }
        }
    }
#undef LOAD_STAGE
#undef COMPUTE_STAGE
}

// ---------------- windowed attention: one CTA per (b, head, window) ----------------
// Warps 0..6 each own 7 consecutive rows -> K/V smem columns read once per 7 rows.
__global__ void attn_kernel(const float* __restrict__ pos_emb)
{
    __shared__ float q_s[64 * 49];    // q^T, reused for o^T
    __shared__ float k_s[64 * 49];
    __shared__ float v_s[64 * 49];
    __shared__ float p_s[49 * 50];
    __shared__ float bias_s[169];

    int t   = threadIdx.x;
    int win = blockIdx.x;
    int h   = blockIdx.y;
    int b   = blockIdx.z;

    int base_hw = ((win >> 3) * 7) * HH + (win & 7) * 7;
    size_t gbase = ((size_t)b * INNER + h * 64) * HW;
    const float* qb = g_q + gbase;
    const float* kb = g_k + gbase;
    const float* vb = g_v + gbase;

    for (int e = t; e < 3136; e += 256) {
        int d = e / 49;
        int j = e - d * 49;
        int off = base_hw + (j / 7) * HH + (j % 7);
        size_t gi = (size_t)d * HW + off;
        q_s[e] = qb[gi];
        k_s[e] = kb[gi];
        v_s[e] = vb[gi];
    }
    if (t < 169) bias_s[t] = pos_emb[t * 8 + h];
    __syncthreads();

    int wid  = t >> 5;
    int lane = t & 31;

    if (wid < 7) {
        int iBase = wid * 7;
        int j0 = lane;
        int j1 = lane + 32;
        int jm = (j1 < 49) ? j1 : 48;

        // ---- QK^T: 7 rows at once, K columns loaded once ----
        float a0[7], a1[7];
#pragma unroll
        for (int r = 0; r < 7; r++) { a0[r] = 0.f; a1[r] = 0.f; }

#pragma unroll 8
        for (int d = 0; d < 64; d++) {
            float kc0 = k_s[d * 49 + j0];
            float kc1 = k_s[d * 49 + jm];
#pragma unroll
            for (int r = 0; r < 7; r++) {
                float qd = q_s[d * 49 + iBase + r];
                a0[r] = fmaf(qd, kc0, a0[r]);
                a1[r] = fmaf(qd, kc1, a1[r]);
            }
        }

        // bias + softmax per row
        int xj0 = j0 / 7, yj0 = j0 - xj0 * 7;
        int xj1 = jm / 7, yj1 = jm - xj1 * 7;
#pragma unroll
        for (int r = 0; r < 7; r++) {
            int i = iBase + r;
            int xi = i / 7, yi = i - xi * 7;
            float v0 = a0[r] * 0.125f + bias_s[(xj0 - xi + 6) * 13 + (yj0 - yi + 6)];
            float v1;
            if (j1 < 49)
                v1 = a1[r] * 0.125f + bias_s[(xj1 - xi + 6) * 13 + (yj1 - yi + 6)];
            else
                v1 = -1e30f;

            float mx = fmaxf(v0, v1);
#pragma unroll
            for (int o = 16; o; o >>= 1) mx = fmaxf(mx, __shfl_xor_sync(0xffffffffu, mx, o));
            float e0 = __expf(v0 - mx);
            float e1 = (j1 < 49) ? __expf(v1 - mx) : 0.f;
            float s = e0 + e1;
#pragma unroll
            for (int o = 16; o; o >>= 1) s += __shfl_xor_sync(0xffffffffu, s, o);
            float inv = 1.f / s;
            p_s[i * 50 + j0] = e0 * inv;
            if (j1 < 49) p_s[i * 50 + j1] = e1 * inv;
        }
        __syncwarp();

        // ---- A @ V: 7 rows at once, V columns loaded once ----
        int d0 = lane, d1 = lane + 32;
        float o0[7], o1[7];
#pragma unroll
        for (int r = 0; r < 7; r++) { o0[r] = 0.f; o1[r] = 0.f; }

#pragma unroll 7
        for (int j = 0; j < 49; j++) {
            float vc0 = v_s[d0 * 49 + j];
            float vc1 = v_s[d1 * 49 + j];
#pragma unroll
            for (int r = 0; r < 7; r++) {
                float p = p_s[(iBase + r) * 50 + j];
                o0[r] = fmaf(p, vc0, o0[r]);
                o1[r] = fmaf(p, vc1, o1[r]);
            }
        }
#pragma unroll
        for (int r = 0; r < 7; r++) {
            q_s[d0 * 49 + iBase + r] = o0[r];
            q_s[d1 * 49 + iBase + r] = o1[r];
        }
    }
    __syncthreads();

    float* ob = g_o + gbase;
    for (int e = t; e < 3136; e += 256) {
        int d = e / 49;
        int j = e - d * 49;
        ob[(size_t)d * HW + base_hw + (j / 7) * HH + (j % 7)] = q_s[e];
    }
}

// ---------------- launch ----------------
extern "C" void kernel_launch(void* const* d_in, const int* in_sizes, int n_in,
                              void* d_out, int out_size)
{
    (void)in_sizes; (void)n_in; (void)out_size;
    const float* x      = (const float*)d_in[0];
    const float* q_dw   = (const float*)d_in[1];
    const float* q_g    = (const float*)d_in[2];
    const float* q_b    = (const float*)d_in[3];
    const float* q_m    = (const float*)d_in[4];
    const float* q_v    = (const float*)d_in[5];
    const float* q_pw   = (const float*)d_in[6];
    const float* k_dw   = (const float*)d_in[7];
    const float* k_g    = (const float*)d_in[8];
    const float* k_b    = (const float*)d_in[9];
    const float* k_m    = (const float*)d_in[10];
    const float* k_v    = (const float*)d_in[11];
    const float* k_pw   = (const float*)d_in[12];
    const float* v_dw   = (const float*)d_in[13];
    const float* v_g    = (const float*)d_in[14];
    const float* v_b    = (const float*)d_in[15];
    const float* v_m    = (const float*)d_in[16];
    const float* v_v    = (const float*)d_in[17];
    const float* v_pw   = (const float*)d_in[18];
    const float* pos    = (const float*)d_in[19];
    const float* out_w  = (const float*)d_in[20];
    const float* out_b  = (const float*)d_in[21];
    float* out          = (float*)d_out;

    float *yq, *yk, *yv, *q, *k, *v, *o;
    cudaGetSymbolAddress((void**)&yq, g_yq);
    cudaGetSymbolAddress((void**)&yk, g_yk);
    cudaGetSymbolAddress((void**)&yv, g_yv);
    cudaGetSymbolAddress((void**)&q,  g_q);
    cudaGetSymbolAddress((void**)&k,  g_k);
    cudaGetSymbolAddress((void**)&v,  g_v);
    cudaGetSymbolAddress((void**)&o,  g_o);

    const int smemBytes = 2 * BUF_FLOATS * sizeof(float);   // 67584
    cudaFuncSetAttribute(gemm_tf32_kernel,
                         cudaFuncAttributeMaxDynamicSharedMemorySize, smemBytes);

    const int dwBlocks = (BATCH * DIMC * HW) / 256;
    dim3 gemmGridQKV(HW / BN, INNER / BM, BATCH);   // (28, 4, 16)
    dim3 gemmGridOut(HW / BN, DIMC / BM, BATCH);    // (28, 2, 16)
    dim3 attnGrid(64, 8, BATCH);

    dw_bn3_kernel<<<dwBlocks, 256>>>(x,
        q_dw, q_g, q_b, q_m, q_v,
        k_dw, k_g, k_b, k_m, k_v,
        v_dw, v_g, v_b, v_m, v_v);
    gemm_tf32_kernel<<<gemmGridQKV, 128, smemBytes>>>(q_pw, nullptr, yq, q, DIMC);
    gemm_tf32_kernel<<<gemmGridQKV, 128, smemBytes>>>(k_pw, nullptr, yk, k, DIMC);
    gemm_tf32_kernel<<<gemmGridQKV, 128, smemBytes>>>(v_pw, nullptr, yv, v, DIMC);
    attn_kernel<<<attnGrid, 256>>>(pos);
    gemm_tf32_kernel<<<gemmGridOut, 128, smemBytes>>>(out_w, out_b, o, out, INNER);
}

// round 16
// speedup vs baseline: 1.1615x; 1.1615x over previous
#include <cuda_runtime.h>
#include <cstdint>

#define DIMC   256
#define INNER  512
#define HH     56
#define HW     3136        // 56*56
#define BATCH  16

// GEMM tiles (r9 configuration — benched 124.8us/launch)
#define BM 128
#define BN 112
#define BK 16
#define AST 20     // As row stride (floats): frag banks = (20g+tig)%32 all-distinct
#define BST 120    // Bs row stride (floats): frag banks = (24tig+g)%32 all-distinct

// Attention smem strides
#define QST 68     // q_s/p_s [token][d]: A-frag banks = (4g+tig)%32 all-distinct
#define PST 68
#define KST 56     // k_s [d][token]: B-frag banks = (24tig+g)%32 all-distinct
#define VST 88     // v_s [token][d]: B-frag banks = (24tig+g)%32 all-distinct
#define OFF_P (64 * QST)
#define OFF_K (OFF_P + 64 * PST)
#define OFF_V (OFF_K + 64 * KST)
#define OFF_BIAS (OFF_V + 56 * VST)
#define ATTN_SMEM_BYTES ((OFF_BIAS + 176) * 4)

// ---------------- scratch (static device globals; no allocation) ----------------
__device__ float g_yq[(size_t)BATCH * DIMC  * HW];
__device__ float g_yk[(size_t)BATCH * DIMC  * HW];
__device__ float g_yv[(size_t)BATCH * DIMC  * HW];
__device__ float g_q[(size_t)BATCH * INNER * HW];
__device__ float g_k[(size_t)BATCH * INNER * HW];
__device__ float g_v[(size_t)BATCH * INNER * HW];
__device__ float g_o[(size_t)BATCH * INNER * HW];

// ---------------- fused 3x depthwise 3x3 conv + BN (eval) ----------------
__global__ void dw_bn3_kernel(const float* __restrict__ x,
                              const float* __restrict__ qw, const float* __restrict__ qg,
                              const float* __restrict__ qb, const float* __restrict__ qm,
                              const float* __restrict__ qv,
                              const float* __restrict__ kw, const float* __restrict__ kg,
                              const float* __restrict__ kb, const float* __restrict__ km,
                              const float* __restrict__ kv,
                              const float* __restrict__ vw, const float* __restrict__ vg,
                              const float* __restrict__ vb, const float* __restrict__ vm,
                              const float* __restrict__ vv)
{
    int idx = blockIdx.x * blockDim.x + threadIdx.x;
    int hw  = idx % HW;
    int bc  = idx / HW;
    int c   = bc % DIMC;
    int h   = hw / HH;
    int wq  = hw - h * HH;

    float qs = qg[c] * rsqrtf(qv[c] + 1e-5f);
    float qbe = qb[c] - qm[c] * qs;
    float ks = kg[c] * rsqrtf(kv[c] + 1e-5f);
    float kbe = kb[c] - km[c] * ks;
    float vs = vg[c] * rsqrtf(vv[c] + 1e-5f);
    float vbe = vb[c] - vm[c] * vs;

    const float* xp = x + (size_t)bc * HW;
    const float* qwp = qw + c * 9;
    const float* kwp = kw + c * 9;
    const float* vwp = vw + c * 9;

    float qa = 0.f, ka = 0.f, va = 0.f;
#pragma unroll
    for (int kh = 0; kh < 3; kh++) {
        int ih = h + kh - 1;
        if (ih < 0 || ih >= HH) continue;
#pragma unroll
        for (int kw2 = 0; kw2 < 3; kw2++) {
            int iw = wq + kw2 - 1;
            if (iw < 0 || iw >= HH) continue;
            float xv = xp[ih * HH + iw];
            int wi = kh * 3 + kw2;
            qa = fmaf(xv, qwp[wi], qa);
            ka = fmaf(xv, kwp[wi], ka);
            va = fmaf(xv, vwp[wi], va);
        }
    }
    g_yq[idx] = qa * qs + qbe;
    g_yk[idx] = ka * ks + kbe;
    g_yv[idx] = va * vs + vbe;
}

// ---------------- shared MMA helpers ----------------
__device__ __forceinline__ uint32_t to_tf32(float x) {
    uint32_t u;
    asm("cvt.rna.tf32.f32 %0, %1;" : "=r"(u) : "f"(x));
    return u;
}

__device__ __forceinline__ void mma_tf32(float* d, const uint32_t* a, const uint32_t* b) {
    asm volatile(
        "mma.sync.aligned.m16n8k8.row.col.f32.tf32.tf32.f32 "
        "{%0,%1,%2,%3}, {%4,%5,%6,%7}, {%8,%9}, {%0,%1,%2,%3};\n"
        : "+f"(d[0]), "+f"(d[1]), "+f"(d[2]), "+f"(d[3])
        : "r"(a[0]), "r"(a[1]), "r"(a[2]), "r"(a[3]), "r"(b[0]), "r"(b[1]));
}

__device__ __forceinline__ void cp16(uint32_t dst, const void* src) {
    asm volatile("cp.async.cg.shared.global [%0], [%1], 16;\n" :: "r"(dst), "l"(src));
}
__device__ __forceinline__ void cpCommit() {
    asm volatile("cp.async.commit_group;\n" ::);
}
template<int N> __device__ __forceinline__ void cpWait() {
    asm volatile("cp.async.wait_group %0;\n" :: "n"(N));
}

// ---------------- TF32 tensor-core GEMM (r9: BK=16, static smem, single sync) ----------------
__global__ void __launch_bounds__(128, 3)
gemm_tf32_kernel(const float* __restrict__ W,
                 const float* __restrict__ bias,
                 const float* __restrict__ src,
                 float* __restrict__ dst,
                 int Kdim)
{
    __shared__ float As[2][BM * AST];   // [m][k] raw f32
    __shared__ float Bs[2][BK * BST];   // [k][n] raw f32

    int b     = blockIdx.z;
    int nBase = blockIdx.x * BN;
    int mBase = blockIdx.y * BM;

    const float* Bb = src + (size_t)b * Kdim * HW;

    int t    = threadIdx.x;
    int wid  = t >> 5;
    int lane = t & 31;
    int g    = lane >> 2;
    int tig  = lane & 3;
    int m0   = (wid >> 1) * 64;
    int n0   = (wid & 1) * 56;

    const float* aPtr = W + (size_t)(mBase + t) * Kdim;

    uint32_t sAb[2], sBb[2];
    sAb[0] = (uint32_t)__cvta_generic_to_shared(&As[0][0]);
    sAb[1] = (uint32_t)__cvta_generic_to_shared(&As[1][0]);
    sBb[0] = (uint32_t)__cvta_generic_to_shared(&Bs[0][0]);
    sBb[1] = (uint32_t)__cvta_generic_to_shared(&Bs[1][0]);

    int bi0  = t;
    int bRow0 = bi0 / 28, bC0 = bi0 - bRow0 * 28;
    int bi1  = t + 128;
    int bRow1 = bi1 / 28, bC1 = bi1 - bRow1 * 28;
    int bi2  = t + 256;
    int bRow2 = bi2 / 28, bC2 = bi2 - bRow2 * 28;
    int bi3  = t + 384;
    int bRow3 = bi3 / 28, bC3 = bi3 - bRow3 * 28;
    bool bAct3 = (bi3 < 448);

    float acc[4][7][4];
#pragma unroll
    for (int i = 0; i < 4; i++)
#pragma unroll
        for (int j = 0; j < 7; j++)
#pragma unroll
            for (int r = 0; r < 4; r++) acc[i][j][r] = 0.f;

    int nStages = Kdim >> 4;

#define LOAD_STAGE(K0, BUF)                                                         \
    {                                                                               \
        uint32_t ad = sAb[BUF] + t * (AST * 4);                                     \
        _Pragma("unroll")                                                           \
        for (int q = 0; q < 4; q++)                                                 \
            cp16(ad + q * 16, aPtr + (K0) + 4 * q);                                 \
        cp16(sBb[BUF] + bRow0 * (BST * 4) + bC0 * 16,                               \
             Bb + (size_t)((K0) + bRow0) * HW + nBase + bC0 * 4);                   \
        cp16(sBb[BUF] + bRow1 * (BST * 4) + bC1 * 16,                               \
             Bb + (size_t)((K0) + bRow1) * HW + nBase + bC1 * 4);                   \
        cp16(sBb[BUF] + bRow2 * (BST * 4) + bC2 * 16,                               \
             Bb + (size_t)((K0) + bRow2) * HW + nBase + bC2 * 4);                   \
        if (bAct3)                                                                  \
            cp16(sBb[BUF] + bRow3 * (BST * 4) + bC3 * 16,                           \
                 Bb + (size_t)((K0) + bRow3) * HW + nBase + bC3 * 4);               \
    }

#define COMPUTE_STAGE(BUF)                                                          \
    {                                                                               \
        _Pragma("unroll")                                                           \
        for (int kk = 0; kk < 2; kk++) {                                            \
            int kb = kk * 8;                                                        \
            uint32_t af[4][4];                                                      \
            uint32_t bf[7][2];                                                      \
            _Pragma("unroll")                                                       \
            for (int im = 0; im < 4; im++) {                                        \
                const float* ap = &As[BUF][(m0 + 16 * im + g) * AST + kb + tig];    \
                af[im][0] = to_tf32(ap[0]);                                         \
                af[im][1] = to_tf32(ap[8 * AST]);                                   \
                af[im][2] = to_tf32(ap[4]);                                         \
                af[im][3] = to_tf32(ap[8 * AST + 4]);                               \
            }                                                                       \
            _Pragma("unroll")                                                       \
            for (int jn = 0; jn < 7; jn++) {                                        \
                const float* bp = &Bs[BUF][(kb + tig) * BST + n0 + 8 * jn + g];     \
                bf[jn][0] = to_tf32(bp[0]);                                         \
                bf[jn][1] = to_tf32(bp[4 * BST]);                                   \
            }                                                                       \
            _Pragma("unroll")                                                       \
            for (int im = 0; im < 4; im++)                                          \
                _Pragma("unroll")                                                   \
                for (int jn = 0; jn < 7; jn++)                                      \
                    mma_tf32(acc[im][jn], af[im], bf[jn]);                          \
        }                                                                           \
    }

    LOAD_STAGE(0, 0);
    cpCommit();

    int buf = 0;
    for (int s = 0; s < nStages; s++) {
        cpWait<0>();
        __syncthreads();
        if (s + 1 < nStages) {
            LOAD_STAGE((s + 1) << 4, buf ^ 1);
            cpCommit();
        }
        COMPUTE_STAGE(buf);
        buf ^= 1;
    }

    float* Cb = dst + (size_t)b * (gridDim.y * BM) * HW;
#pragma unroll
    for (int im = 0; im < 4; im++) {
#pragma unroll
        for (int r2 = 0; r2 < 2; r2++) {
            int m = mBase + m0 + 16 * im + g + 8 * r2;
            float bi = bias ? bias[m] : 0.f;
#pragma unroll
            for (int jn = 0; jn < 7; jn++) {
                int n = nBase + n0 + 8 * jn + 2 * tig;
                float2 val = make_float2(acc[im][jn][2 * r2] + bi,
                                         acc[im][jn][2 * r2 + 1] + bi);
                *(float2*)(Cb + (size_t)m * HW + n) = val;
            }
        }
    }
#undef LOAD_STAGE
#undef COMPUTE_STAGE
}

// ---------------- MMA windowed attention: one CTA per (b, head, window) ----------------
// 128 threads = 4 warps; warp w owns M-rows [16w, 16w+16).
// QK^T: A = q_s [i][d] row-major, B = k_s [d][j] ([k][n]) -> scores in mma accum layout.
// Softmax: quad shfl (rows live at fixed g across tig). Probs -> p_s [i][j].
// AV: A = p_s [i][j], B = v_s [j][d] ([k][n]). Output -> q_s (reuse) -> scatter.
extern __shared__ float attn_sm[];

__global__ void __launch_bounds__(128)
attn_kernel(const float* __restrict__ pos_emb)
{
    float* q_s    = attn_sm;                // [64][QST]  (q, later o)
    float* p_s    = attn_sm + OFF_P;        // [64][PST]
    float* k_s    = attn_sm + OFF_K;        // [64][KST]  ([d][j])
    float* v_s    = attn_sm + OFF_V;        // [56][VST]  ([j][d])
    float* bias_s = attn_sm + OFF_BIAS;     // [169]

    int t   = threadIdx.x;
    int win = blockIdx.x;
    int h   = blockIdx.y;
    int b   = blockIdx.z;

    int base_hw = ((win >> 3) * 7) * HH + (win & 7) * 7;
    size_t gbase = ((size_t)b * INNER + h * 64) * HW;
    const float* qb = g_q + gbase;
    const float* kb = g_k + gbase;
    const float* vb = g_v + gbase;

    // gather
    for (int e = t; e < 3136; e += 128) {
        int d = e / 49;
        int j = e - d * 49;
        int off = base_hw + (j / 7) * HH + (j % 7);
        size_t gi = (size_t)d * HW + off;
        float qv = qb[gi], kv = kb[gi], vv = vb[gi];
        q_s[j * QST + d] = qv;
        k_s[d * KST + j] = kv;
        v_s[j * VST + d] = vv;
    }
    // zero V pad rows (tokens 49..55) so 0-prob x garbage can't make NaN
    for (int e = t; e < 7 * VST; e += 128) v_s[49 * VST + e] = 0.f;
    for (int e = t; e < 169; e += 128) bias_s[e] = pos_emb[e * 8 + h];
    __syncthreads();

    int wid  = t >> 5;
    int lane = t & 31;
    int g    = lane >> 2;
    int tig  = lane & 3;
    int m0   = wid * 16;

    // ---- QK^T ----
    float c[7][4];
#pragma unroll
    for (int jn = 0; jn < 7; jn++)
#pragma unroll
        for (int r = 0; r < 4; r++) c[jn][r] = 0.f;

#pragma unroll
    for (int k8 = 0; k8 < 8; k8++) {
        int kbs = 8 * k8;
        uint32_t af[4];
        const float* ap = &q_s[(m0 + g) * QST + kbs + tig];
        af[0] = to_tf32(ap[0]);
        af[1] = to_tf32(ap[8 * QST]);
        af[2] = to_tf32(ap[4]);
        af[3] = to_tf32(ap[8 * QST + 4]);
#pragma unroll
        for (int jn = 0; jn < 7; jn++) {
            uint32_t bf[2];
            const float* bp = &k_s[(kbs + tig) * KST + 8 * jn + g];
            bf[0] = to_tf32(bp[0]);
            bf[1] = to_tf32(bp[4 * KST]);
            mma_tf32(c[jn], af, bf);
        }
    }

    // ---- bias + mask + softmax (rows i0 = m0+g, i1 = m0+8+g) ----
    int i0 = m0 + g, i1 = m0 + 8 + g;
    int xi0 = i0 / 7, yi0 = i0 - 7 * xi0;
    int xi1 = i1 / 7, yi1 = i1 - 7 * xi1;

    float mx0 = -1e30f, mx1 = -1e30f;
#pragma unroll
    for (int jn = 0; jn < 7; jn++) {
#pragma unroll
        for (int hh = 0; hh < 2; hh++) {
            int col = 8 * jn + 2 * tig + hh;
            if (col < 49) {
                int xj = col / 7, yj = col - 7 * xj;
                c[jn][hh]     = c[jn][hh]     * 0.125f + bias_s[(xj - xi0 + 6) * 13 + (yj - yi0 + 6)];
                c[jn][2 + hh] = c[jn][2 + hh] * 0.125f + bias_s[(xj - xi1 + 6) * 13 + (yj - yi1 + 6)];
            } else {
                c[jn][hh] = -1e30f;
                c[jn][2 + hh] = -1e30f;
            }
            mx0 = fmaxf(mx0, c[jn][hh]);
            mx1 = fmaxf(mx1, c[jn][2 + hh]);
        }
    }
    mx0 = fmaxf(mx0, __shfl_xor_sync(0xffffffffu, mx0, 1));
    mx0 = fmaxf(mx0, __shfl_xor_sync(0xffffffffu, mx0, 2));
    mx1 = fmaxf(mx1, __shfl_xor_sync(0xffffffffu, mx1, 1));
    mx1 = fmaxf(mx1, __shfl_xor_sync(0xffffffffu, mx1, 2));

    float s0 = 0.f, s1 = 0.f;
#pragma unroll
    for (int jn = 0; jn < 7; jn++) {
#pragma unroll
        for (int hh = 0; hh < 2; hh++) {
            c[jn][hh]     = __expf(c[jn][hh] - mx0);
            c[jn][2 + hh] = __expf(c[jn][2 + hh] - mx1);
            s0 += c[jn][hh];
            s1 += c[jn][2 + hh];
        }
    }
    s0 += __shfl_xor_sync(0xffffffffu, s0, 1);
    s0 += __shfl_xor_sync(0xffffffffu, s0, 2);
    s1 += __shfl_xor_sync(0xffffffffu, s1, 1);
    s1 += __shfl_xor_sync(0xffffffffu, s1, 2);
    float inv0 = 1.f / s0, inv1 = 1.f / s1;

#pragma unroll
    for (int jn = 0; jn < 7; jn++) {
        *(float2*)&p_s[i0 * PST + 8 * jn + 2 * tig] =
            make_float2(c[jn][0] * inv0, c[jn][1] * inv0);
        *(float2*)&p_s[i1 * PST + 8 * jn + 2 * tig] =
            make_float2(c[jn][2] * inv1, c[jn][3] * inv1);
    }
    __syncwarp();

    // ---- AV: O = P @ V ----
    float o[8][4];
#pragma unroll
    for (int dn = 0; dn < 8; dn++)
#pragma unroll
        for (int r = 0; r < 4; r++) o[dn][r] = 0.f;

#pragma unroll
    for (int k7 = 0; k7 < 7; k7++) {
        int kbs = 8 * k7;
        uint32_t af[4];
        const float* ap = &p_s[(m0 + g) * PST + kbs + tig];
        af[0] = to_tf32(ap[0]);
        af[1] = to_tf32(ap[8 * PST]);
        af[2] = to_tf32(ap[4]);
        af[3] = to_tf32(ap[8 * PST + 4]);
#pragma unroll
        for (int dn = 0; dn < 8; dn++) {
            uint32_t bf[2];
            const float* bp = &v_s[(kbs + tig) * VST + 8 * dn + g];
            bf[0] = to_tf32(bp[0]);
            bf[1] = to_tf32(bp[4 * VST]);
            mma_tf32(o[dn], af, bf);
        }
    }

    // store O rows (<49) into q_s (reuse; each warp touches only its own rows)
    if (i0 < 49) {
#pragma unroll
        for (int dn = 0; dn < 8; dn++)
            *(float2*)&q_s[i0 * QST + 8 * dn + 2 * tig] = make_float2(o[dn][0], o[dn][1]);
    }
    if (i1 < 49) {
#pragma unroll
        for (int dn = 0; dn < 8; dn++)
            *(float2*)&q_s[i1 * QST + 8 * dn + 2 * tig] = make_float2(o[dn][2], o[dn][3]);
    }
    __syncthreads();

    // scatter
    float* ob = g_o + gbase;
    for (int e = t; e < 3136; e += 128) {
        int d = e / 49;
        int j = e - d * 49;
        ob[(size_t)d * HW + base_hw + (j / 7) * HH + (j % 7)] = q_s[j * QST + d];
    }
}

// ---------------- launch ----------------
extern "C" void kernel_launch(void* const* d_in, const int* in_sizes, int n_in,
                              void* d_out, int out_size)
{
    (void)in_sizes; (void)n_in; (void)out_size;
    const float* x      = (const float*)d_in[0];
    const float* q_dw   = (const float*)d_in[1];
    const float* q_g    = (const float*)d_in[2];
    const float* q_b    = (const float*)d_in[3];
    const float* q_m    = (const float*)d_in[4];
    const float* q_v    = (const float*)d_in[5];
    const float* q_pw   = (const float*)d_in[6];
    const float* k_dw   = (const float*)d_in[7];
    const float* k_g    = (const float*)d_in[8];
    const float* k_b    = (const float*)d_in[9];
    const float* k_m    = (const float*)d_in[10];
    const float* k_v    = (const float*)d_in[11];
    const float* k_pw   = (const float*)d_in[12];
    const float* v_dw   = (const float*)d_in[13];
    const float* v_g    = (const float*)d_in[14];
    const float* v_b    = (const float*)d_in[15];
    const float* v_m    = (const float*)d_in[16];
    const float* v_v    = (const float*)d_in[17];
    const float* v_pw   = (const float*)d_in[18];
    const float* pos    = (const float*)d_in[19];
    const float* out_w  = (const float*)d_in[20];
    const float* out_b  = (const float*)d_in[21];
    float* out          = (float*)d_out;

    float *yq, *yk, *yv, *q, *k, *v, *o;
    cudaGetSymbolAddress((void**)&yq, g_yq);
    cudaGetSymbolAddress((void**)&yk, g_yk);
    cudaGetSymbolAddress((void**)&yv, g_yv);
    cudaGetSymbolAddress((void**)&q,  g_q);
    cudaGetSymbolAddress((void**)&k,  g_k);
    cudaGetSymbolAddress((void**)&v,  g_v);
    cudaGetSymbolAddress((void**)&o,  g_o);

    cudaFuncSetAttribute(attn_kernel,
                         cudaFuncAttributeMaxDynamicSharedMemorySize, ATTN_SMEM_BYTES);

    const int dwBlocks = (BATCH * DIMC * HW) / 256;
    dim3 gemmGridQKV(HW / BN, INNER / BM, BATCH);   // (28, 4, 16)
    dim3 gemmGridOut(HW / BN, DIMC / BM, BATCH);    // (28, 2, 16)
    dim3 attnGrid(64, 8, BATCH);

    dw_bn3_kernel<<<dwBlocks, 256>>>(x,
        q_dw, q_g, q_b, q_m, q_v,
        k_dw, k_g, k_b, k_m, k_v,
        v_dw, v_g, v_b, v_m, v_v);
    gemm_tf32_kernel<<<gemmGridQKV, 128>>>(q_pw, nullptr, yq, q, DIMC);
    gemm_tf32_kernel<<<gemmGridQKV, 128>>>(k_pw, nullptr, yk, k, DIMC);
    gemm_tf32_kernel<<<gemmGridQKV, 128>>>(v_pw, nullptr, yv, v, DIMC);
    attn_kernel<<<attnGrid, 128, ATTN_SMEM_BYTES>>>(pos);
    gemm_tf32_kernel<<<gemmGridOut, 128>>>(out_w, out_b, o, out, INNER);
}